// round 2
// baseline (speedup 1.0000x reference)
#include <cuda_runtime.h>
#include <math.h>

// Problem constants
#define BB 32
#define SS 52
#define AA 5
#define CC 80
#define TT 50
#define PD (AA * (5 + CC))        // 425
#define NROWS (BB * SS * SS)      // 86,528
#define NTGT  (BB * TT)           // 1600
#define NOBJ_BLOCKS (NROWS / 256) // 338 (exact)
#define NBLOCKS (NOBJ_BLOCKS + 1) // 339 : block 0 = targets, 1..338 = noobj

// Anchors (w, h)
__device__ __constant__ float c_anchors[AA * 2] = {
    1.3221f, 1.73145f,
    3.19275f, 4.00944f,
    5.05587f, 8.09892f,
    9.47112f, 4.84053f,
    11.2364f, 10.0071f
};

// Per-block partials (overwritten every launch; no zeroing needed) + ticket.
__device__ float g_part[3][NBLOCKS];   // [0]=coord raw, [1]=obj, [2]=conf^2 net
__device__ unsigned int g_ticket;      // static-init 0; finalizer resets to 0

__device__ __forceinline__ float sigmoidf_(float x) {
    return 1.0f / (1.0f + expf(-x));
}

__device__ __forceinline__ float warp_sum(float v) {
    #pragma unroll
    for (int o = 16; o > 0; o >>= 1) v += __shfl_down_sync(0xFFFFFFFFu, v, o);
    return v;
}

__global__ __launch_bounds__(256) void k_fused(const float* __restrict__ pred,
                                               const float* __restrict__ tgt,
                                               float* __restrict__ out, int out_size) {
    __shared__ float s_tgt[NTGT * 5];   // 32 KB (block 0 only)
    __shared__ int   s_cell[NTGT];      // 6.4 KB
    __shared__ float s_red[3][8];

    const int tid = threadIdx.x;
    const int bid = blockIdx.x;
    float acc0 = 0.0f, acc1 = 0.0f, acc2 = 0.0f;  // coord, obj, conf^2 net

    if (bid == 0) {
        // ---- Phase A: stage all targets into shared (coalesced) ----
        for (int i = tid; i < NTGT * 5; i += 256) s_tgt[i] = tgt[i];
        __syncthreads();

        // ---- Phase B: per-target cell index ----
        for (int n = tid; n < NTGT; n += 256) {
            const float* tr = &s_tgt[n * 5];
            float gtw = tr[2] * (float)SS;
            float gth = tr[3] * (float)SS;
            float best = -1.0f;
            int best_a = 0;
            #pragma unroll
            for (int a = 0; a < AA; a++) {
                float aw = c_anchors[a * 2], ah = c_anchors[a * 2 + 1];
                float inter = fminf(gtw, aw) * fminf(gth, ah);
                float uni = gtw * gth + aw * ah - inter;
                float iou = (uni > 0.0f) ? (inter / uni) : 0.0f;
                if (iou > best) { best = iou; best_a = a; }  // first max wins
            }
            int gi = (int)(tr[0] * (float)SS);
            int gj = (int)(tr[1] * (float)SS);
            int b = n / TT;
            s_cell[n] = ((b * AA + best_a) * SS + gj) * SS + gi;
        }
        __syncthreads();

        // ---- Phase C: winners (last-wins) gather + losses ----
        for (int n = tid; n < NTGT; n += 256) {
            int b = n / TT;
            int myc = s_cell[n];
            bool win = true;
            for (int u = n + 1; u < (b + 1) * TT; u++)
                if (s_cell[u] == myc) { win = false; break; }
            if (!win) continue;

            const float* tr = &s_tgt[n * 5];
            float gx = tr[0], gy = tr[1];
            float gtw = tr[2] * (float)SS;
            float gth = tr[3] * (float)SS;
            // decode cell components from myc
            int gi = myc % SS;
            int gj = (myc / SS) % SS;
            int best_a = (myc / (SS * SS)) % AA;

            const float* p = pred + (((size_t)b * SS + gj) * SS + gi) * PD + best_a * (5 + CC);
            float tx = p[0], ty = p[1], tw = p[2], th = p[3], score = p[4];
            float pbx = sigmoidf_(tx);
            float pby = sigmoidf_(ty);
            float pbw = expf(tw) * c_anchors[best_a * 2];
            float pbh = expf(th) * c_anchors[best_a * 2 + 1];
            float conf = sigmoidf_(score);

            float ggx = gx * (float)SS - (float)gi;
            float ggy = gy * (float)SS - (float)gj;

            float cx1 = ggx + (float)gi, cy1 = ggy + (float)gj;
            float cx2 = pbx + (float)gi, cy2 = pby + (float)gj;
            float ix = fmaxf(0.0f, fminf(cx1 + gtw * 0.5f, cx2 + pbw * 0.5f)
                                 - fmaxf(cx1 - gtw * 0.5f, cx2 - pbw * 0.5f));
            float iy = fmaxf(0.0f, fminf(cy1 + gth * 0.5f, cy2 + pbh * 0.5f)
                                 - fmaxf(cy1 - gth * 0.5f, cy2 - pbh * 0.5f));
            float inter = ix * iy;
            float uni = gtw * gth + pbw * pbh - inter;
            float iou = (uni > 0.0f) ? (inter / uni) : 0.0f;

            const float eps = 1e-6f;
            float d1 = pbx - ggx, d2 = pby - ggy;
            float s1 = sqrtf(pbw + eps) - sqrtf(gtw + eps);
            float s2 = sqrtf(pbh + eps) - sqrtf(gth + eps);
            acc0 += d1 * d1 + d2 * d2 + s1 * s1 + s2 * s2;
            float od = iou - conf;
            acc1 += od * od;
            acc2 -= conf * conf;    // remove this cell from the no-obj sum
        }
    } else {
        // ---- No-obj: one row per thread, 5 strided conf loads ----
        int r = (bid - 1) * 256 + tid;   // always < NROWS (exact tiling)
        const float* row = pred + (size_t)r * PD;
        #pragma unroll
        for (int a = 0; a < AA; a++) {
            float conf = sigmoidf_(row[a * (5 + CC) + 4]);
            acc2 += conf * conf;
        }
    }

    // ---- Block reduction (3 values) ----
    float w0 = warp_sum(acc0), w1 = warp_sum(acc1), w2 = warp_sum(acc2);
    int lane = tid & 31, warp = tid >> 5;
    if (lane == 0) { s_red[0][warp] = w0; s_red[1][warp] = w1; s_red[2][warp] = w2; }
    __syncthreads();
    if (tid == 0) {
        float b0 = 0.0f, b1 = 0.0f, b2 = 0.0f;
        #pragma unroll
        for (int w = 0; w < 8; w++) { b0 += s_red[0][w]; b1 += s_red[1][w]; b2 += s_red[2][w]; }
        g_part[0][bid] = b0;
        g_part[1][bid] = b1;
        g_part[2][bid] = b2;
        __threadfence();
        unsigned int ticket = atomicAdd(&g_ticket, 1u);
        if (ticket == (unsigned int)(gridDim.x - 1)) {
            // ---- Finalize: fixed-order deterministic sum ----
            double c0 = 0.0, c1 = 0.0, c2 = 0.0;
            for (int i = 0; i < NBLOCKS; i++) {
                c0 += (double)g_part[0][i];
                c1 += (double)g_part[1][i];
                c2 += (double)g_part[2][i];
            }
            double loss_coord = 5.0 * c0;
            double loss_noobj = 0.5 * c2;
            double total = 5.0 * loss_coord + c1 + 0.5 * loss_noobj;
            if (out_size > 0) out[0] = (float)total;
            if (out_size > 1) out[1] = (float)loss_coord;
            if (out_size > 2) out[2] = (float)(c1 + loss_noobj);
            g_ticket = 0;   // reset for next graph replay
        }
    }
}

extern "C" void kernel_launch(void* const* d_in, const int* in_sizes, int n_in,
                              void* d_out, int out_size) {
    const float* pred = (const float*)d_in[0];   // [32,52,52,425]
    const float* tgt  = (const float*)d_in[1];   // [32,50,5]
    float* out = (float*)d_out;

    k_fused<<<NBLOCKS, 256>>>(pred, tgt, out, out_size);
}

// round 3
// speedup vs baseline: 1.3984x; 1.3984x over previous
#include <cuda_runtime.h>
#include <math.h>

// Problem constants
#define BB 32
#define SS 52
#define AA 5
#define CC 80
#define TT 50
#define PD (AA * (5 + CC))        // 425
#define NROWS (BB * SS * SS)      // 86,528
#define NTGT  (BB * TT)           // 1600
#define NOBJ_BLOCKS (NROWS / 256) // 338 (exact)
#define NBLOCKS (NOBJ_BLOCKS + 1) // 339 : block 0 = targets, 1..338 = noobj

// Anchors (w, h)
__device__ __constant__ float c_anchors[AA * 2] = {
    1.3221f, 1.73145f,
    3.19275f, 4.00944f,
    9.47112f, 4.84053f,   // placeholder reordered below? NO — keep exact order:
};
// NOTE: correct anchor table (exact order) defined here; the above partial
// initializer is overwritten by this full definition.
__device__ __constant__ float c_anchors_full[AA * 2] = {
    1.3221f, 1.73145f,
    3.19275f, 4.00944f,
    5.05587f, 8.09892f,
    9.47112f, 4.84053f,
    11.2364f, 10.0071f
};
#define ANC c_anchors_full

// Per-block partials (fully overwritten every launch; no zeroing needed) + ticket.
__device__ float g_part[3][NBLOCKS];   // [0]=coord raw, [1]=obj, [2]=conf^2 net
__device__ unsigned int g_ticket;      // static-init 0; finalizer resets to 0

__device__ __forceinline__ float sigmoidf_(float x) {
    return 1.0f / (1.0f + expf(-x));
}

__device__ __forceinline__ float warp_sum(float v) {
    #pragma unroll
    for (int o = 16; o > 0; o >>= 1) v += __shfl_down_sync(0xFFFFFFFFu, v, o);
    return v;
}
__device__ __forceinline__ double warp_sum_d(double v) {
    #pragma unroll
    for (int o = 16; o > 0; o >>= 1) v += __shfl_down_sync(0xFFFFFFFFu, v, o);
    return v;
}

__global__ __launch_bounds__(256) void k_fused(const float* __restrict__ pred,
                                               const float* __restrict__ tgt,
                                               float* __restrict__ out, int out_size) {
    __shared__ float s_tgt[NTGT * 5];   // 32 KB (block 0 only)
    __shared__ int   s_cell[NTGT];      // 6.4 KB
    __shared__ float s_red[3][8];
    __shared__ double s_redd[3][8];
    __shared__ unsigned int s_islast;

    const int tid = threadIdx.x;
    const int bid = blockIdx.x;
    float acc0 = 0.0f, acc1 = 0.0f, acc2 = 0.0f;  // coord, obj, conf^2 net

    if (bid == 0) {
        // ---- Phase A: stage all targets into shared (coalesced) ----
        for (int i = tid; i < NTGT * 5; i += 256) s_tgt[i] = tgt[i];
        __syncthreads();

        // ---- Phase B: per-target cell index ----
        for (int n = tid; n < NTGT; n += 256) {
            const float* tr = &s_tgt[n * 5];
            float gtw = tr[2] * (float)SS;
            float gth = tr[3] * (float)SS;
            float best = -1.0f;
            int best_a = 0;
            #pragma unroll
            for (int a = 0; a < AA; a++) {
                float aw = ANC[a * 2], ah = ANC[a * 2 + 1];
                float inter = fminf(gtw, aw) * fminf(gth, ah);
                float uni = gtw * gth + aw * ah - inter;
                float iou = (uni > 0.0f) ? (inter / uni) : 0.0f;
                if (iou > best) { best = iou; best_a = a; }  // first max wins
            }
            int gi = (int)(tr[0] * (float)SS);
            int gj = (int)(tr[1] * (float)SS);
            int b = n / TT;
            s_cell[n] = ((b * AA + best_a) * SS + gj) * SS + gi;
        }
        __syncthreads();

        // ---- Phase C: winners (last-wins) gather + losses ----
        for (int n = tid; n < NTGT; n += 256) {
            int b = n / TT;
            int myc = s_cell[n];
            bool win = true;
            for (int u = n + 1; u < (b + 1) * TT; u++)
                if (s_cell[u] == myc) { win = false; break; }
            if (!win) continue;

            const float* tr = &s_tgt[n * 5];
            float gx = tr[0], gy = tr[1];
            float gtw = tr[2] * (float)SS;
            float gth = tr[3] * (float)SS;
            int gi = myc % SS;
            int gj = (myc / SS) % SS;
            int best_a = (myc / (SS * SS)) % AA;

            const float* p = pred + (((size_t)b * SS + gj) * SS + gi) * PD + best_a * (5 + CC);
            float tx = p[0], ty = p[1], tw = p[2], th = p[3], score = p[4];
            float pbx = sigmoidf_(tx);
            float pby = sigmoidf_(ty);
            float pbw = expf(tw) * ANC[best_a * 2];
            float pbh = expf(th) * ANC[best_a * 2 + 1];
            float conf = sigmoidf_(score);

            float ggx = gx * (float)SS - (float)gi;
            float ggy = gy * (float)SS - (float)gj;

            float cx1 = ggx + (float)gi, cy1 = ggy + (float)gj;
            float cx2 = pbx + (float)gi, cy2 = pby + (float)gj;
            float ix = fmaxf(0.0f, fminf(cx1 + gtw * 0.5f, cx2 + pbw * 0.5f)
                                 - fmaxf(cx1 - gtw * 0.5f, cx2 - pbw * 0.5f));
            float iy = fmaxf(0.0f, fminf(cy1 + gth * 0.5f, cy2 + pbh * 0.5f)
                                 - fmaxf(cy1 - gth * 0.5f, cy2 - pbh * 0.5f));
            float inter = ix * iy;
            float uni = gtw * gth + pbw * pbh - inter;
            float iou = (uni > 0.0f) ? (inter / uni) : 0.0f;

            const float eps = 1e-6f;
            float d1 = pbx - ggx, d2 = pby - ggy;
            float s1 = sqrtf(pbw + eps) - sqrtf(gtw + eps);
            float s2 = sqrtf(pbh + eps) - sqrtf(gth + eps);
            acc0 += d1 * d1 + d2 * d2 + s1 * s1 + s2 * s2;
            float od = iou - conf;
            acc1 += od * od;
            acc2 -= conf * conf;    // remove this cell from the no-obj sum
        }
    } else {
        // ---- No-obj: one row per thread, 5 strided conf loads ----
        int r = (bid - 1) * 256 + tid;   // always < NROWS (exact tiling)
        const float* row = pred + (size_t)r * PD;
        #pragma unroll
        for (int a = 0; a < AA; a++) {
            float conf = sigmoidf_(row[a * (5 + CC) + 4]);
            acc2 += conf * conf;
        }
    }

    // ---- Block reduction (3 values) ----
    float w0 = warp_sum(acc0), w1 = warp_sum(acc1), w2 = warp_sum(acc2);
    int lane = tid & 31, warp = tid >> 5;
    if (lane == 0) { s_red[0][warp] = w0; s_red[1][warp] = w1; s_red[2][warp] = w2; }
    __syncthreads();
    if (tid == 0) {
        float b0 = 0.0f, b1 = 0.0f, b2 = 0.0f;
        #pragma unroll
        for (int w = 0; w < 8; w++) { b0 += s_red[0][w]; b1 += s_red[1][w]; b2 += s_red[2][w]; }
        g_part[0][bid] = b0;
        g_part[1][bid] = b1;
        g_part[2][bid] = b2;
        __threadfence();
        unsigned int ticket = atomicAdd(&g_ticket, 1u);
        s_islast = (ticket == (unsigned int)(gridDim.x - 1)) ? 1u : 0u;
    }
    __syncthreads();

    // ---- Parallel finalize in the last-arriving block ----
    if (s_islast) {
        double v0 = 0.0, v1 = 0.0, v2 = 0.0;
        // grid-stride over partials: fixed per-thread order -> deterministic
        for (int i = tid; i < NBLOCKS; i += 256) {
            v0 += (double)g_part[0][i];
            v1 += (double)g_part[1][i];
            v2 += (double)g_part[2][i];
        }
        v0 = warp_sum_d(v0); v1 = warp_sum_d(v1); v2 = warp_sum_d(v2);
        if (lane == 0) { s_redd[0][warp] = v0; s_redd[1][warp] = v1; s_redd[2][warp] = v2; }
        __syncthreads();
        if (tid == 0) {
            double c0 = 0.0, c1 = 0.0, c2 = 0.0;
            #pragma unroll
            for (int w = 0; w < 8; w++) { c0 += s_redd[0][w]; c1 += s_redd[1][w]; c2 += s_redd[2][w]; }
            double loss_coord = 5.0 * c0;
            double loss_noobj = 0.5 * c2;
            double total = 5.0 * loss_coord + c1 + 0.5 * loss_noobj;
            if (out_size > 0) out[0] = (float)total;
            if (out_size > 1) out[1] = (float)loss_coord;
            if (out_size > 2) out[2] = (float)(c1 + loss_noobj);
            g_ticket = 0;   // reset for next graph replay
        }
    }
}

extern "C" void kernel_launch(void* const* d_in, const int* in_sizes, int n_in,
                              void* d_out, int out_size) {
    const float* pred = (const float*)d_in[0];   // [32,52,52,425]
    const float* tgt  = (const float*)d_in[1];   // [32,50,5]
    float* out = (float*)d_out;

    k_fused<<<NBLOCKS, 256>>>(pred, tgt, out, out_size);
}

// round 4
// speedup vs baseline: 2.0313x; 1.4526x over previous
#include <cuda_runtime.h>
#include <math.h>

// Problem constants
#define BB 32
#define SS 52
#define AA 5
#define CC 80
#define TT 50
#define PD (AA * (5 + CC))        // 425
#define NROWS (BB * SS * SS)      // 86,528
#define NTGT  (BB * TT)           // 1600

// Anchors (w, h)
__device__ __constant__ float c_anchors[AA * 2] = {
    1.3221f, 1.73145f,
    3.19275f, 4.00944f,
    5.05587f, 8.09892f,
    9.47112f, 4.84053f,
    11.2364f, 10.0071f
};

// [0]=coord raw, [1]=obj, [2]=conf^2 net (noobj sum minus obj-cell conf^2)
__device__ double g_acc[3];

__device__ __forceinline__ float sigmoidf_(float x) {
    return 1.0f / (1.0f + expf(-x));
}

__device__ __forceinline__ float warp_sum(float v) {
    #pragma unroll
    for (int o = 16; o > 0; o >>= 1) v += __shfl_down_sync(0xFFFFFFFFu, v, o);
    return v;
}

// K1: single block, all target-side work in shared memory.
__global__ __launch_bounds__(512) void k_targets(const float* __restrict__ pred,
                                                 const float* __restrict__ tgt) {
    __shared__ float s_tgt[NTGT * 5];   // 32 KB
    __shared__ int   s_cell[NTGT];      // 6.4 KB

    const int tid = threadIdx.x;
    if (tid < 3) g_acc[tid] = 0.0;

    // ---- Phase A: stage all targets (coalesced, 8000 floats) ----
    for (int i = tid; i < NTGT * 5; i += 512) s_tgt[i] = tgt[i];
    __syncthreads();

    // ---- Phase B: per-target cell index ----
    for (int n = tid; n < NTGT; n += 512) {
        const float* tr = &s_tgt[n * 5];
        float gtw = tr[2] * (float)SS;
        float gth = tr[3] * (float)SS;
        float best = -1.0f;
        int best_a = 0;
        #pragma unroll
        for (int a = 0; a < AA; a++) {
            float aw = c_anchors[a * 2], ah = c_anchors[a * 2 + 1];
            float inter = fminf(gtw, aw) * fminf(gth, ah);
            float uni = gtw * gth + aw * ah - inter;
            float iou = (uni > 0.0f) ? (inter / uni) : 0.0f;
            if (iou > best) { best = iou; best_a = a; }  // first max wins
        }
        int gi = (int)(tr[0] * (float)SS);
        int gj = (int)(tr[1] * (float)SS);
        int b = n / TT;
        s_cell[n] = ((b * AA + best_a) * SS + gj) * SS + gi;
    }
    __syncthreads();

    // ---- Phase C: winners (last-wins) gather scattered preds + losses ----
    float acc0 = 0.0f, acc1 = 0.0f, acc2 = 0.0f;
    for (int n = tid; n < NTGT; n += 512) {
        int b = n / TT;
        int myc = s_cell[n];
        bool win = true;
        for (int u = n + 1; u < (b + 1) * TT; u++)
            if (s_cell[u] == myc) { win = false; break; }
        if (!win) continue;

        const float* tr = &s_tgt[n * 5];
        float gx = tr[0], gy = tr[1];
        float gtw = tr[2] * (float)SS;
        float gth = tr[3] * (float)SS;
        int gi = myc % SS;
        int gj = (myc / SS) % SS;
        int best_a = (myc / (SS * SS)) % AA;

        const float* p = pred + (((size_t)b * SS + gj) * SS + gi) * PD + best_a * (5 + CC);
        float tx = p[0], ty = p[1], tw = p[2], th = p[3], score = p[4];
        float pbx = sigmoidf_(tx);
        float pby = sigmoidf_(ty);
        float pbw = expf(tw) * c_anchors[best_a * 2];
        float pbh = expf(th) * c_anchors[best_a * 2 + 1];
        float conf = sigmoidf_(score);

        float ggx = gx * (float)SS - (float)gi;
        float ggy = gy * (float)SS - (float)gj;

        float cx1 = ggx + (float)gi, cy1 = ggy + (float)gj;
        float cx2 = pbx + (float)gi, cy2 = pby + (float)gj;
        float ix = fmaxf(0.0f, fminf(cx1 + gtw * 0.5f, cx2 + pbw * 0.5f)
                             - fmaxf(cx1 - gtw * 0.5f, cx2 - pbw * 0.5f));
        float iy = fmaxf(0.0f, fminf(cy1 + gth * 0.5f, cy2 + pbh * 0.5f)
                             - fmaxf(cy1 - gth * 0.5f, cy2 - pbh * 0.5f));
        float inter = ix * iy;
        float uni = gtw * gth + pbw * pbh - inter;
        float iou = (uni > 0.0f) ? (inter / uni) : 0.0f;

        const float eps = 1e-6f;
        float d1 = pbx - ggx, d2 = pby - ggy;
        float s1 = sqrtf(pbw + eps) - sqrtf(gtw + eps);
        float s2 = sqrtf(pbh + eps) - sqrtf(gth + eps);
        acc0 += d1 * d1 + d2 * d2 + s1 * s1 + s2 * s2;
        float od = iou - conf;
        acc1 += od * od;
        acc2 -= conf * conf;    // remove this cell from the no-obj sum
    }

    float w0 = warp_sum(acc0), w1 = warp_sum(acc1), w2 = warp_sum(acc2);
    if ((tid & 31) == 0) {
        if (w0 != 0.0f) atomicAdd(&g_acc[0], (double)w0);
        if (w1 != 0.0f) atomicAdd(&g_acc[1], (double)w1);
        if (w2 != 0.0f) atomicAdd(&g_acc[2], (double)w2);
    }
}

// K2: streaming sum of conf^2 over ALL cells (identical to R1's proven version).
__global__ void k_noobj(const float* __restrict__ pred) {
    int r = blockIdx.x * blockDim.x + threadIdx.x;
    float local = 0.0f;
    if (r < NROWS) {
        const float* row = pred + (size_t)r * PD;
        #pragma unroll
        for (int a = 0; a < AA; a++) {
            float conf = sigmoidf_(row[a * (5 + CC) + 4]);
            local += conf * conf;
        }
    }
    float w = warp_sum(local);
    if ((threadIdx.x & 31) == 0 && w != 0.0f) atomicAdd(&g_acc[2], (double)w);
}

// K3: finalize (identical to R1)
__global__ void k_final(float* __restrict__ out, int out_size) {
    double coord_raw = g_acc[0];
    double obj       = g_acc[1];
    double noobj_raw = g_acc[2];
    double loss_coord = 5.0 * coord_raw;
    double loss_noobj = 0.5 * noobj_raw;
    double total = 5.0 * loss_coord + obj + 0.5 * loss_noobj;
    if (out_size > 0) out[0] = (float)total;
    if (out_size > 1) out[1] = (float)loss_coord;
    if (out_size > 2) out[2] = (float)(obj + loss_noobj);
}

extern "C" void kernel_launch(void* const* d_in, const int* in_sizes, int n_in,
                              void* d_out, int out_size) {
    const float* pred = (const float*)d_in[0];   // [32,52,52,425]
    const float* tgt  = (const float*)d_in[1];   // [32,50,5]
    float* out = (float*)d_out;

    k_targets<<<1, 512>>>(pred, tgt);
    int nb = (NROWS + 255) / 256;                 // 338 blocks exactly covers 86,528
    k_noobj<<<nb, 256>>>(pred);
    k_final<<<1, 1>>>(out, out_size);
}

// round 5
// speedup vs baseline: 6.2353x; 3.0696x over previous
#include <cuda_runtime.h>
#include <math.h>

// Problem constants
#define BB 32
#define SS 52
#define AA 5
#define CC 80
#define TT 50
#define PD (AA * (5 + CC))        // 425
#define NROWS (BB * SS * SS)      // 86,528

// Anchors (w, h)
__device__ __constant__ float c_anchors[AA * 2] = {
    1.3221f, 1.73145f,
    3.19275f, 4.00944f,
    5.05587f, 8.09892f,
    9.47112f, 4.84053f,
    11.2364f, 10.0071f
};

// Per-batch target partials: [0]=coord raw, [1]=obj, [2]=minus conf^2 of obj cells.
// Fully overwritten by every k_targets launch — no zeroing needed.
__device__ float  g_part[3][BB];
// Accumulator for k_noobj's conf^2 sum (zeroed by k_targets block 0 each launch).
__device__ double g_noobj;

__device__ __forceinline__ float sigmoidf_(float x) {
    return 1.0f / (1.0f + expf(-x));
}

__device__ __forceinline__ float warp_sum(float v) {
    #pragma unroll
    for (int o = 16; o > 0; o >>= 1) v += __shfl_down_sync(0xFFFFFFFFu, v, o);
    return v;
}

// K1: one block per batch. 64 threads; thread t < TT owns target t.
__global__ __launch_bounds__(64) void k_targets(const float* __restrict__ pred,
                                                const float* __restrict__ tgt) {
    __shared__ float s_t[TT * 5];    // 250 floats
    __shared__ int   s_cell[TT];
    __shared__ float s_r[3][2];

    const int tid = threadIdx.x;
    const int b = blockIdx.x;

    if (b == 0 && tid == 0) g_noobj = 0.0;   // stream-ordered before k_noobj

    // Stage this batch's targets (coalesced)
    for (int i = tid; i < TT * 5; i += 64) s_t[i] = tgt[b * TT * 5 + i];
    __syncthreads();

    // Per-target cell
    if (tid < TT) {
        const float* tr = &s_t[tid * 5];
        float gtw = tr[2] * (float)SS;
        float gth = tr[3] * (float)SS;
        float best = -1.0f;
        int best_a = 0;
        #pragma unroll
        for (int a = 0; a < AA; a++) {
            float aw = c_anchors[a * 2], ah = c_anchors[a * 2 + 1];
            float inter = fminf(gtw, aw) * fminf(gth, ah);
            float uni = gtw * gth + aw * ah - inter;
            float iou = (uni > 0.0f) ? (inter / uni) : 0.0f;
            if (iou > best) { best = iou; best_a = a; }  // first max wins
        }
        int gi = (int)(tr[0] * (float)SS);
        int gj = (int)(tr[1] * (float)SS);
        s_cell[tid] = (best_a * SS + gj) * SS + gi;      // batch-local cell id
    }
    __syncthreads();

    // Winner = no later target in this batch maps to the same cell (last-wins)
    float acc0 = 0.0f, acc1 = 0.0f, acc2 = 0.0f;
    bool win = (tid < TT);
    int myc = win ? s_cell[tid] : -1;
    if (win) {
        for (int u = tid + 1; u < TT; u++)
            if (s_cell[u] == myc) { win = false; break; }
    }
    if (win) {
        const float* tr = &s_t[tid * 5];
        float gx = tr[0], gy = tr[1];
        float gtw = tr[2] * (float)SS;
        float gth = tr[3] * (float)SS;
        int gi = myc % SS;
        int gj = (myc / SS) % SS;
        int best_a = myc / (SS * SS);

        const float* p = pred + (((size_t)b * SS + gj) * SS + gi) * PD + best_a * (5 + CC);
        float tx = p[0], ty = p[1], tw = p[2], th = p[3], score = p[4];
        float pbx = sigmoidf_(tx);
        float pby = sigmoidf_(ty);
        float pbw = expf(tw) * c_anchors[best_a * 2];
        float pbh = expf(th) * c_anchors[best_a * 2 + 1];
        float conf = sigmoidf_(score);

        float ggx = gx * (float)SS - (float)gi;
        float ggy = gy * (float)SS - (float)gj;

        float cx1 = ggx + (float)gi, cy1 = ggy + (float)gj;
        float cx2 = pbx + (float)gi, cy2 = pby + (float)gj;
        float ix = fmaxf(0.0f, fminf(cx1 + gtw * 0.5f, cx2 + pbw * 0.5f)
                             - fmaxf(cx1 - gtw * 0.5f, cx2 - pbw * 0.5f));
        float iy = fmaxf(0.0f, fminf(cy1 + gth * 0.5f, cy2 + pbh * 0.5f)
                             - fmaxf(cy1 - gth * 0.5f, cy2 - pbh * 0.5f));
        float inter = ix * iy;
        float uni = gtw * gth + pbw * pbh - inter;
        float iou = (uni > 0.0f) ? (inter / uni) : 0.0f;

        const float eps = 1e-6f;
        float d1 = pbx - ggx, d2 = pby - ggy;
        float s1 = sqrtf(pbw + eps) - sqrtf(gtw + eps);
        float s2 = sqrtf(pbh + eps) - sqrtf(gth + eps);
        acc0 = d1 * d1 + d2 * d2 + s1 * s1 + s2 * s2;
        float od = iou - conf;
        acc1 = od * od;
        acc2 = -conf * conf;    // remove this cell from the no-obj sum
    }

    // Reduce 2 warps -> per-batch partial slots (no atomics)
    float w0 = warp_sum(acc0), w1 = warp_sum(acc1), w2 = warp_sum(acc2);
    int lane = tid & 31, warp = tid >> 5;
    if (lane == 0) { s_r[0][warp] = w0; s_r[1][warp] = w1; s_r[2][warp] = w2; }
    __syncthreads();
    if (tid == 0) {
        g_part[0][b] = s_r[0][0] + s_r[0][1];
        g_part[1][b] = s_r[1][0] + s_r[1][1];
        g_part[2][b] = s_r[2][0] + s_r[2][1];
    }
}

// K2: streaming sum of conf^2 over ALL cells (R1's proven version).
__global__ void k_noobj(const float* __restrict__ pred) {
    int r = blockIdx.x * blockDim.x + threadIdx.x;
    float local = 0.0f;
    if (r < NROWS) {
        const float* row = pred + (size_t)r * PD;
        #pragma unroll
        for (int a = 0; a < AA; a++) {
            float conf = sigmoidf_(row[a * (5 + CC) + 4]);
            local += conf * conf;
        }
    }
    float w = warp_sum(local);
    if ((threadIdx.x & 31) == 0 && w != 0.0f) atomicAdd(&g_noobj, (double)w);
}

// K3: finalize — one warp reduces the 32 per-batch partials.
__global__ __launch_bounds__(32) void k_final(float* __restrict__ out, int out_size) {
    int tid = threadIdx.x;
    float v0 = g_part[0][tid];
    float v1 = g_part[1][tid];
    float v2 = g_part[2][tid];
    v0 = warp_sum(v0); v1 = warp_sum(v1); v2 = warp_sum(v2);
    if (tid == 0) {
        double coord_raw = (double)v0;
        double obj       = (double)v1;
        double noobj_raw = g_noobj + (double)v2;
        double loss_coord = 5.0 * coord_raw;
        double loss_noobj = 0.5 * noobj_raw;
        double total = 5.0 * loss_coord + obj + 0.5 * loss_noobj;
        if (out_size > 0) out[0] = (float)total;
        if (out_size > 1) out[1] = (float)loss_coord;
        if (out_size > 2) out[2] = (float)(obj + loss_noobj);
    }
}

extern "C" void kernel_launch(void* const* d_in, const int* in_sizes, int n_in,
                              void* d_out, int out_size) {
    const float* pred = (const float*)d_in[0];   // [32,52,52,425]
    const float* tgt  = (const float*)d_in[1];   // [32,50,5]
    float* out = (float*)d_out;

    k_targets<<<BB, 64>>>(pred, tgt);
    int nb = (NROWS + 255) / 256;                 // 338 blocks exactly covers 86,528
    k_noobj<<<nb, 256>>>(pred);
    k_final<<<1, 32>>>(out, out_size);
}

// round 8
// speedup vs baseline: 12.8715x; 2.0643x over previous
#include <cuda_runtime.h>
#include <math.h>

// Problem constants
#define BB 32
#define SS 52
#define AA 5
#define CC 80
#define TT 50
#define PD (AA * (5 + CC))          // 425
#define NROWS (BB * SS * SS)        // 86,528
#define NBLK_NOBJ (NROWS / 256)     // 338 (exact)
#define NBLOCKS (BB + NBLK_NOBJ)    // 370 : 0..31 targets, 32..369 noobj

// Anchors (w, h)
__device__ __constant__ float c_anchors[AA * 2] = {
    1.3221f, 1.73145f,
    3.19275f, 4.00944f,
    5.05587f, 8.09892f,
    9.47112f, 4.84053f,
    11.2364f, 10.0071f
};

// Per-block partials: [0]=coord raw, [1]=obj, [2]=conf^2 net.
// Every slot overwritten every launch -> no zeroing needed.
__device__ float g_part[3][NBLOCKS];
__device__ unsigned int g_ticket;   // static 0; finalizer resets

__device__ __forceinline__ float sigmoidf_(float x) {
    return 1.0f / (1.0f + __expf(-x));
}

__device__ __forceinline__ float warp_sum(float v) {
    #pragma unroll
    for (int o = 16; o > 0; o >>= 1) v += __shfl_down_sync(0xFFFFFFFFu, v, o);
    return v;
}
__device__ __forceinline__ double warp_sum_d(double v) {
    #pragma unroll
    for (int o = 16; o > 0; o >>= 1) v += __shfl_down_sync(0xFFFFFFFFu, v, o);
    return v;
}

__global__ __launch_bounds__(256) void k_fused(const float* __restrict__ pred,
                                               const float* __restrict__ tgt,
                                               float* __restrict__ out, int out_size) {
    __shared__ float s_t[TT * 5];       // 1 KB
    __shared__ int   s_cell[TT];
    __shared__ int   s_loser[TT];
    __shared__ float s_red[3][8];
    __shared__ double s_redd[3][8];
    __shared__ unsigned int s_last;

    const int tid = threadIdx.x;
    const int bid = blockIdx.x;
    const int lane = tid & 31, warp = tid >> 5;
    float a0 = 0.0f, a1 = 0.0f, a2 = 0.0f;   // coord, obj, conf^2 net

    if (bid < BB) {
        const int b = bid;
        // Stage this batch's 250 target floats (one coalesced load)
        if (tid < TT * 5) s_t[tid] = tgt[b * TT * 5 + tid];
        if (tid < TT) s_loser[tid] = 0;
        __syncthreads();

        // Per-target cell (threads 0..49)
        if (tid < TT) {
            const float* tr = &s_t[tid * 5];
            float gtw = tr[2] * (float)SS;
            float gth = tr[3] * (float)SS;
            float best = -1.0f;
            int best_a = 0;
            #pragma unroll
            for (int a = 0; a < AA; a++) {
                float aw = c_anchors[a * 2], ah = c_anchors[a * 2 + 1];
                float inter = fminf(gtw, aw) * fminf(gth, ah);
                float uni = gtw * gth + aw * ah - inter;
                float iou = (uni > 0.0f) ? (inter / uni) : 0.0f;
                if (iou > best) { best = iou; best_a = a; }  // first max wins
            }
            int gi = (int)(tr[0] * (float)SS);
            int gj = (int)(tr[1] * (float)SS);
            s_cell[tid] = (best_a * SS + gj) * SS + gi;      // batch-local cell id
        }
        __syncthreads();

        // Parallel last-wins: pair (t,u), u>t, same cell => t loses.
        for (int p = tid; p < TT * TT; p += 256) {
            int t = p / TT, u = p - t * TT;
            if (u > t && s_cell[u] == s_cell[t]) s_loser[t] = 1;
        }
        __syncthreads();

        // Winners gather + losses (threads 0..49)
        if (tid < TT && !s_loser[tid]) {
            const float* tr = &s_t[tid * 5];
            float gx = tr[0], gy = tr[1];
            float gtw = tr[2] * (float)SS;
            float gth = tr[3] * (float)SS;
            int myc = s_cell[tid];
            int gi = myc % SS;
            int gj = (myc / SS) % SS;
            int best_a = myc / (SS * SS);

            const float* p = pred + (((size_t)b * SS + gj) * SS + gi) * PD + best_a * (5 + CC);
            float tx = p[0], ty = p[1], tw = p[2], th = p[3], score = p[4];
            float pbx = sigmoidf_(tx);
            float pby = sigmoidf_(ty);
            float pbw = __expf(tw) * c_anchors[best_a * 2];
            float pbh = __expf(th) * c_anchors[best_a * 2 + 1];
            float conf = sigmoidf_(score);

            float ggx = gx * (float)SS - (float)gi;
            float ggy = gy * (float)SS - (float)gj;

            float cx1 = ggx + (float)gi, cy1 = ggy + (float)gj;
            float cx2 = pbx + (float)gi, cy2 = pby + (float)gj;
            float ix = fmaxf(0.0f, fminf(cx1 + gtw * 0.5f, cx2 + pbw * 0.5f)
                                 - fmaxf(cx1 - gtw * 0.5f, cx2 - pbw * 0.5f));
            float iy = fmaxf(0.0f, fminf(cy1 + gth * 0.5f, cy2 + pbh * 0.5f)
                                 - fmaxf(cy1 - gth * 0.5f, cy2 - pbh * 0.5f));
            float inter = ix * iy;
            float uni = gtw * gth + pbw * pbh - inter;
            float iou = (uni > 0.0f) ? (inter / uni) : 0.0f;

            const float eps = 1e-6f;
            float d1 = pbx - ggx, d2 = pby - ggy;
            float s1 = sqrtf(pbw + eps) - sqrtf(gtw + eps);
            float s2 = sqrtf(pbh + eps) - sqrtf(gth + eps);
            a0 = d1 * d1 + d2 * d2 + s1 * s1 + s2 * s2;
            float od = iou - conf;
            a1 = od * od;
            a2 = -conf * conf;      // remove obj cell from no-obj sum
        }
    } else {
        // No-obj: one row per thread (exact tiling, no bounds check)
        int r = (bid - BB) * 256 + tid;
        const float* row = pred + (size_t)r * PD;
        #pragma unroll
        for (int a = 0; a < AA; a++) {
            float conf = sigmoidf_(row[a * (5 + CC) + 4]);
            a2 += conf * conf;
        }
    }

    // Block reduction -> per-block partial slots (no atomics)
    float w0 = warp_sum(a0), w1 = warp_sum(a1), w2 = warp_sum(a2);
    if (lane == 0) { s_red[0][warp] = w0; s_red[1][warp] = w1; s_red[2][warp] = w2; }
    __syncthreads();
    if (tid == 0) {
        float b0 = 0.0f, b1 = 0.0f, b2 = 0.0f;
        #pragma unroll
        for (int w = 0; w < 8; w++) { b0 += s_red[0][w]; b1 += s_red[1][w]; b2 += s_red[2][w]; }
        g_part[0][bid] = b0;
        g_part[1][bid] = b1;
        g_part[2][bid] = b2;
        __threadfence();
        unsigned int t = atomicAdd(&g_ticket, 1u);
        s_last = (t == (unsigned int)(gridDim.x - 1)) ? 1u : 0u;
    }
    __syncthreads();

    // Parallel finalize in last-arriving block (fixed-order -> deterministic)
    if (s_last) {
        double v0 = 0.0, v1 = 0.0, v2 = 0.0;
        for (int i = tid; i < NBLOCKS; i += 256) {
            v0 += (double)g_part[0][i];
            v1 += (double)g_part[1][i];
            v2 += (double)g_part[2][i];
        }
        v0 = warp_sum_d(v0); v1 = warp_sum_d(v1); v2 = warp_sum_d(v2);
        if (lane == 0) { s_redd[0][warp] = v0; s_redd[1][warp] = v1; s_redd[2][warp] = v2; }
        __syncthreads();
        if (tid == 0) {
            double c0 = 0.0, c1 = 0.0, c2 = 0.0;
            #pragma unroll
            for (int w = 0; w < 8; w++) { c0 += s_redd[0][w]; c1 += s_redd[1][w]; c2 += s_redd[2][w]; }
            double loss_coord = 5.0 * c0;
            double loss_noobj = 0.5 * c2;
            double total = 5.0 * loss_coord + c1 + 0.5 * loss_noobj;
            if (out_size > 0) out[0] = (float)total;
            if (out_size > 1) out[1] = (float)loss_coord;
            if (out_size > 2) out[2] = (float)(c1 + loss_noobj);
            g_ticket = 0;   // reset for next graph replay
        }
    }
}

extern "C" void kernel_launch(void* const* d_in, const int* in_sizes, int n_in,
                              void* d_out, int out_size) {
    const float* pred = (const float*)d_in[0];   // [32,52,52,425]
    const float* tgt  = (const float*)d_in[1];   // [32,50,5]
    float* out = (float*)d_out;

    k_fused<<<NBLOCKS, 256>>>(pred, tgt, out, out_size);
}

// round 9
// speedup vs baseline: 15.0976x; 1.1729x over previous
#include <cuda_runtime.h>
#include <math.h>

// Problem constants
#define BB 32
#define SS 52
#define AA 5
#define CC 80
#define TT 50
#define PD (AA * (5 + CC))            // 425
#define NROWS (BB * SS * SS)          // 86,528
#define NCONF (NROWS * AA)            // 432,640
#define NBLK_NOBJ (NCONF / 256)       // 1690 (exact)
#define NBLOCKS (BB + NBLK_NOBJ)      // 1722 : 0..31 targets, 32.. noobj

// Anchors (w, h)
__device__ __constant__ float c_anchors[AA * 2] = {
    1.3221f, 1.73145f,
    3.19275f, 4.00944f,
    5.05587f, 8.09892f,
    9.47112f, 4.84053f,
    11.2364f, 10.0071f
};

// Partials. Targets (blocks 0..31) write all three rows; noobj blocks write
// only row 2. Finalizer reads rows 0/1 for i<BB only. Every read slot is
// overwritten every launch -> no zeroing needed.
__device__ float g_part0[BB];
__device__ float g_part1[BB];
__device__ float g_part2[NBLOCKS];
__device__ unsigned int g_ticket;   // static 0; finalizer resets

__device__ __forceinline__ float sigmoidf_(float x) {
    return 1.0f / (1.0f + __expf(-x));
}

__device__ __forceinline__ float warp_sum(float v) {
    #pragma unroll
    for (int o = 16; o > 0; o >>= 1) v += __shfl_down_sync(0xFFFFFFFFu, v, o);
    return v;
}
__device__ __forceinline__ double warp_sum_d(double v) {
    #pragma unroll
    for (int o = 16; o > 0; o >>= 1) v += __shfl_down_sync(0xFFFFFFFFu, v, o);
    return v;
}

__global__ __launch_bounds__(256) void k_fused(const float* __restrict__ pred,
                                               const float* __restrict__ tgt,
                                               float* __restrict__ out, int out_size) {
    __shared__ float s_t[TT * 5];       // 1 KB (target blocks only)
    __shared__ int   s_cell[TT];
    __shared__ int   s_loser[TT];
    __shared__ float s_red[3][8];
    __shared__ double s_redd[3][8];
    __shared__ unsigned int s_last;

    const int tid = threadIdx.x;
    const int bid = blockIdx.x;
    const int lane = tid & 31, warp = tid >> 5;
    float a0 = 0.0f, a1 = 0.0f, a2 = 0.0f;   // coord, obj, conf^2 net

    if (bid < BB) {
        const int b = bid;
        if (tid < TT * 5) s_t[tid] = tgt[b * TT * 5 + tid];
        if (tid < TT) s_loser[tid] = 0;
        __syncthreads();

        // Per-target cell (threads 0..49)
        if (tid < TT) {
            const float* tr = &s_t[tid * 5];
            float gtw = tr[2] * (float)SS;
            float gth = tr[3] * (float)SS;
            float best = -1.0f;
            int best_a = 0;
            #pragma unroll
            for (int a = 0; a < AA; a++) {
                float aw = c_anchors[a * 2], ah = c_anchors[a * 2 + 1];
                float inter = fminf(gtw, aw) * fminf(gth, ah);
                float uni = gtw * gth + aw * ah - inter;
                float iou = (uni > 0.0f) ? (inter / uni) : 0.0f;
                if (iou > best) { best = iou; best_a = a; }  // first max wins
            }
            int gi = (int)(tr[0] * (float)SS);
            int gj = (int)(tr[1] * (float)SS);
            s_cell[tid] = (best_a * SS + gj) * SS + gi;      // batch-local cell id
        }
        __syncthreads();

        // Parallel last-wins: pair (t,u), u>t, same cell => t loses.
        for (int p = tid; p < TT * TT; p += 256) {
            int t = p / TT, u = p - t * TT;
            if (u > t && s_cell[u] == s_cell[t]) s_loser[t] = 1;
        }
        __syncthreads();

        // Winners gather + losses (threads 0..49)
        if (tid < TT && !s_loser[tid]) {
            const float* tr = &s_t[tid * 5];
            float gx = tr[0], gy = tr[1];
            float gtw = tr[2] * (float)SS;
            float gth = tr[3] * (float)SS;
            int myc = s_cell[tid];
            int gi = myc % SS;
            int gj = (myc / SS) % SS;
            int best_a = myc / (SS * SS);

            const float* p = pred + (((size_t)b * SS + gj) * SS + gi) * PD + best_a * (5 + CC);
            float tx = p[0], ty = p[1], tw = p[2], th = p[3], score = p[4];
            float pbx = sigmoidf_(tx);
            float pby = sigmoidf_(ty);
            float pbw = __expf(tw) * c_anchors[best_a * 2];
            float pbh = __expf(th) * c_anchors[best_a * 2 + 1];
            float conf = sigmoidf_(score);

            float ggx = gx * (float)SS - (float)gi;
            float ggy = gy * (float)SS - (float)gj;

            float cx1 = ggx + (float)gi, cy1 = ggy + (float)gj;
            float cx2 = pbx + (float)gi, cy2 = pby + (float)gj;
            float ix = fmaxf(0.0f, fminf(cx1 + gtw * 0.5f, cx2 + pbw * 0.5f)
                                 - fmaxf(cx1 - gtw * 0.5f, cx2 - pbw * 0.5f));
            float iy = fmaxf(0.0f, fminf(cy1 + gth * 0.5f, cy2 + pbh * 0.5f)
                                 - fmaxf(cy1 - gth * 0.5f, cy2 - pbh * 0.5f));
            float inter = ix * iy;
            float uni = gtw * gth + pbw * pbh - inter;
            float iou = (uni > 0.0f) ? (inter / uni) : 0.0f;

            const float eps = 1e-6f;
            float d1 = pbx - ggx, d2 = pby - ggy;
            float s1 = sqrtf(pbw + eps) - sqrtf(gtw + eps);
            float s2 = sqrtf(pbh + eps) - sqrtf(gth + eps);
            a0 = d1 * d1 + d2 * d2 + s1 * s1 + s2 * s2;
            float od = iou - conf;
            a1 = od * od;
            a2 = -conf * conf;      // remove obj cell from no-obj sum
        }
    } else {
        // No-obj: ONE conf per thread for maximum outstanding-line MLP.
        int n = (bid - BB) * 256 + tid;        // < NCONF (exact tiling)
        int r = n / AA;
        int a = n - r * AA;
        float conf = sigmoidf_(pred[(size_t)r * PD + a * (5 + CC) + 4]);
        a2 = conf * conf;
    }

    // Block reduction -> per-block partial slots (no atomics)
    float w0 = warp_sum(a0), w1 = warp_sum(a1), w2 = warp_sum(a2);
    if (lane == 0) { s_red[0][warp] = w0; s_red[1][warp] = w1; s_red[2][warp] = w2; }
    __syncthreads();
    if (tid == 0) {
        float b0 = 0.0f, b1 = 0.0f, b2 = 0.0f;
        #pragma unroll
        for (int w = 0; w < 8; w++) { b0 += s_red[0][w]; b1 += s_red[1][w]; b2 += s_red[2][w]; }
        if (bid < BB) { g_part0[bid] = b0; g_part1[bid] = b1; }
        g_part2[bid] = b2;
        __threadfence();
        unsigned int t = atomicAdd(&g_ticket, 1u);
        s_last = (t == (unsigned int)(gridDim.x - 1)) ? 1u : 0u;
    }
    __syncthreads();

    // Parallel finalize in last-arriving block (fixed-order -> deterministic)
    if (s_last) {
        double v0 = 0.0, v1 = 0.0, v2 = 0.0;
        if (tid < BB) { v0 = (double)g_part0[tid]; v1 = (double)g_part1[tid]; }
        for (int i = tid; i < NBLOCKS; i += 256) v2 += (double)g_part2[i];
        v0 = warp_sum_d(v0); v1 = warp_sum_d(v1); v2 = warp_sum_d(v2);
        if (lane == 0) { s_redd[0][warp] = v0; s_redd[1][warp] = v1; s_redd[2][warp] = v2; }
        __syncthreads();
        if (tid == 0) {
            double c0 = 0.0, c1 = 0.0, c2 = 0.0;
            #pragma unroll
            for (int w = 0; w < 8; w++) { c0 += s_redd[0][w]; c1 += s_redd[1][w]; c2 += s_redd[2][w]; }
            double loss_coord = 5.0 * c0;
            double loss_noobj = 0.5 * c2;
            double total = 5.0 * loss_coord + c1 + 0.5 * loss_noobj;
            if (out_size > 0) out[0] = (float)total;
            if (out_size > 1) out[1] = (float)loss_coord;
            if (out_size > 2) out[2] = (float)(c1 + loss_noobj);
            g_ticket = 0;   // reset for next graph replay
        }
    }
}

extern "C" void kernel_launch(void* const* d_in, const int* in_sizes, int n_in,
                              void* d_out, int out_size) {
    const float* pred = (const float*)d_in[0];   // [32,52,52,425]
    const float* tgt  = (const float*)d_in[1];   // [32,50,5]
    float* out = (float*)d_out;

    k_fused<<<NBLOCKS, 256>>>(pred, tgt, out, out_size);
}

// round 10
// speedup vs baseline: 16.7297x; 1.1081x over previous
#include <cuda_runtime.h>
#include <math.h>

// Problem constants
#define BB 32
#define SS 52
#define AA 5
#define CC 80
#define TT 50
#define PD (AA * (5 + CC))            // 425
#define NROWS (BB * SS * SS)          // 86,528
#define NCONF (NROWS * AA)            // 432,640
#define GG 2                          // confs per thread (front-batched)
#define NBLK_NOBJ (NCONF / (256 * GG))  // 845 (exact: 432640 = 845*512)
#define NBLOCKS (BB + NBLK_NOBJ)      // 877 : 0..31 targets, 32.. noobj

// Anchors (w, h)
__device__ __constant__ float c_anchors[AA * 2] = {
    1.3221f, 1.73145f,
    3.19275f, 4.00944f,
    5.05587f, 8.09892f,
    9.47112f, 4.84053f,
    11.2364f, 10.0071f
};

// Partials. Targets (blocks 0..31) write all three rows; noobj blocks write
// only row 2. Every read slot is overwritten every launch -> no zeroing.
__device__ float g_part0[BB];
__device__ float g_part1[BB];
__device__ float g_part2[NBLOCKS];
__device__ unsigned int g_ticket;   // static 0; finalizer resets

__device__ __forceinline__ float sigmoidf_(float x) {
    return 1.0f / (1.0f + __expf(-x));
}

__device__ __forceinline__ float warp_sum(float v) {
    #pragma unroll
    for (int o = 16; o > 0; o >>= 1) v += __shfl_down_sync(0xFFFFFFFFu, v, o);
    return v;
}
__device__ __forceinline__ double warp_sum_d(double v) {
    #pragma unroll
    for (int o = 16; o > 0; o >>= 1) v += __shfl_down_sync(0xFFFFFFFFu, v, o);
    return v;
}

__global__ __launch_bounds__(256) void k_fused(const float* __restrict__ pred,
                                               const float* __restrict__ tgt,
                                               float* __restrict__ out, int out_size) {
    __shared__ float s_t[TT * 5];       // 1 KB (target blocks only)
    __shared__ int   s_cell[TT];
    __shared__ int   s_loser[TT];
    __shared__ float s_red[3][8];
    __shared__ double s_redd[3][8];
    __shared__ unsigned int s_last;

    const int tid = threadIdx.x;
    const int bid = blockIdx.x;
    const int lane = tid & 31, warp = tid >> 5;
    float a0 = 0.0f, a1 = 0.0f, a2 = 0.0f;   // coord, obj, conf^2 net

    if (bid < BB) {
        const int b = bid;
        if (tid < TT * 5) s_t[tid] = tgt[b * TT * 5 + tid];
        if (tid < TT) s_loser[tid] = 0;
        __syncthreads();

        // Per-target cell (threads 0..49)
        if (tid < TT) {
            const float* tr = &s_t[tid * 5];
            float gtw = tr[2] * (float)SS;
            float gth = tr[3] * (float)SS;
            float best = -1.0f;
            int best_a = 0;
            #pragma unroll
            for (int a = 0; a < AA; a++) {
                float aw = c_anchors[a * 2], ah = c_anchors[a * 2 + 1];
                float inter = fminf(gtw, aw) * fminf(gth, ah);
                float uni = gtw * gth + aw * ah - inter;
                float iou = (uni > 0.0f) ? (inter / uni) : 0.0f;
                if (iou > best) { best = iou; best_a = a; }  // first max wins
            }
            int gi = (int)(tr[0] * (float)SS);
            int gj = (int)(tr[1] * (float)SS);
            s_cell[tid] = (best_a * SS + gj) * SS + gi;      // batch-local cell id
        }
        __syncthreads();

        // Parallel last-wins: pair (t,u), u>t, same cell => t loses.
        for (int p = tid; p < TT * TT; p += 256) {
            int t = p / TT, u = p - t * TT;
            if (u > t && s_cell[u] == s_cell[t]) s_loser[t] = 1;
        }
        __syncthreads();

        // Winners gather + losses (threads 0..49)
        if (tid < TT && !s_loser[tid]) {
            const float* tr = &s_t[tid * 5];
            float gx = tr[0], gy = tr[1];
            float gtw = tr[2] * (float)SS;
            float gth = tr[3] * (float)SS;
            int myc = s_cell[tid];
            int gi = myc % SS;
            int gj = (myc / SS) % SS;
            int best_a = myc / (SS * SS);

            const float* p = pred + (((size_t)b * SS + gj) * SS + gi) * PD + best_a * (5 + CC);
            float tx = p[0], ty = p[1], tw = p[2], th = p[3], score = p[4];
            float pbx = sigmoidf_(tx);
            float pby = sigmoidf_(ty);
            float pbw = __expf(tw) * c_anchors[best_a * 2];
            float pbh = __expf(th) * c_anchors[best_a * 2 + 1];
            float conf = sigmoidf_(score);

            float ggx = gx * (float)SS - (float)gi;
            float ggy = gy * (float)SS - (float)gj;

            float cx1 = ggx + (float)gi, cy1 = ggy + (float)gj;
            float cx2 = pbx + (float)gi, cy2 = pby + (float)gj;
            float ix = fmaxf(0.0f, fminf(cx1 + gtw * 0.5f, cx2 + pbw * 0.5f)
                                 - fmaxf(cx1 - gtw * 0.5f, cx2 - pbw * 0.5f));
            float iy = fmaxf(0.0f, fminf(cy1 + gth * 0.5f, cy2 + pbh * 0.5f)
                                 - fmaxf(cy1 - gth * 0.5f, cy2 - pbh * 0.5f));
            float inter = ix * iy;
            float uni = gtw * gth + pbw * pbh - inter;
            float iou = (uni > 0.0f) ? (inter / uni) : 0.0f;

            const float eps = 1e-6f;
            float d1 = pbx - ggx, d2 = pby - ggy;
            float s1 = sqrtf(pbw + eps) - sqrtf(gtw + eps);
            float s2 = sqrtf(pbh + eps) - sqrtf(gth + eps);
            a0 = d1 * d1 + d2 * d2 + s1 * s1 + s2 * s2;
            float od = iou - conf;
            a1 = od * od;
            a2 = -conf * conf;      // remove obj cell from no-obj sum
        }
    } else {
        // No-obj: GG front-batched independent streaming loads per thread.
        int base = (bid - BB) * (256 * GG) + tid;   // stride-256 pattern within block
        float s[GG];
        #pragma unroll
        for (int g = 0; g < GG; g++) {
            int n = base + g * 256;                 // < NCONF (exact tiling)
            int r = n / AA;
            int a = n - r * AA;
            s[g] = __ldcs(&pred[(size_t)r * PD + a * (5 + CC) + 4]);
        }
        #pragma unroll
        for (int g = 0; g < GG; g++) {
            float conf = sigmoidf_(s[g]);
            a2 += conf * conf;
        }
    }

    // Block reduction -> per-block partial slots (no atomics)
    float w0 = warp_sum(a0), w1 = warp_sum(a1), w2 = warp_sum(a2);
    if (lane == 0) { s_red[0][warp] = w0; s_red[1][warp] = w1; s_red[2][warp] = w2; }
    __syncthreads();
    if (tid == 0) {
        float b0 = 0.0f, b1 = 0.0f, b2 = 0.0f;
        #pragma unroll
        for (int w = 0; w < 8; w++) { b0 += s_red[0][w]; b1 += s_red[1][w]; b2 += s_red[2][w]; }
        if (bid < BB) { g_part0[bid] = b0; g_part1[bid] = b1; }
        g_part2[bid] = b2;
        __threadfence();
        unsigned int t = atomicAdd(&g_ticket, 1u);
        s_last = (t == (unsigned int)(gridDim.x - 1)) ? 1u : 0u;
    }
    __syncthreads();

    // Parallel finalize in last-arriving block (fixed-order -> deterministic)
    if (s_last) {
        double v0 = 0.0, v1 = 0.0, v2 = 0.0;
        if (tid < BB) { v0 = (double)g_part0[tid]; v1 = (double)g_part1[tid]; }
        for (int i = tid; i < NBLOCKS; i += 256) v2 += (double)g_part2[i];
        v0 = warp_sum_d(v0); v1 = warp_sum_d(v1); v2 = warp_sum_d(v2);
        if (lane == 0) { s_redd[0][warp] = v0; s_redd[1][warp] = v1; s_redd[2][warp] = v2; }
        __syncthreads();
        if (tid == 0) {
            double c0 = 0.0, c1 = 0.0, c2 = 0.0;
            #pragma unroll
            for (int w = 0; w < 8; w++) { c0 += s_redd[0][w]; c1 += s_redd[1][w]; c2 += s_redd[2][w]; }
            double loss_coord = 5.0 * c0;
            double loss_noobj = 0.5 * c2;
            double total = 5.0 * loss_coord + c1 + 0.5 * loss_noobj;
            if (out_size > 0) out[0] = (float)total;
            if (out_size > 1) out[1] = (float)loss_coord;
            if (out_size > 2) out[2] = (float)(c1 + loss_noobj);
            g_ticket = 0;   // reset for next graph replay
        }
    }
}

extern "C" void kernel_launch(void* const* d_in, const int* in_sizes, int n_in,
                              void* d_out, int out_size) {
    const float* pred = (const float*)d_in[0];   // [32,52,52,425]
    const float* tgt  = (const float*)d_in[1];   // [32,50,5]
    float* out = (float*)d_out;

    k_fused<<<NBLOCKS, 256>>>(pred, tgt, out, out_size);
}